// round 13
// baseline (speedup 1.0000x reference)
#include <cuda_runtime.h>

// DeformableCONV: modulated deformable conv v2, depthwise (groups = C).
// x:       (B, C, H, W)           f32
// offsets: (B, 2*C*KK, H, W)      f32   layout (B, C, KK, 2{dy,dx}, H, W)
// mask:    (B, C*KK, H, W)        f32   layout (B, C, KK, H, W)
// weight:  (C, 1, K, K)           f32
// bias:    (C,)                   f32
// out:     (B, C, H, W)           f32

#define B_ 32
#define C_ 17
#define H_ 96
#define W_ 72
#define KK_ 9
#define HW_ (H_ * W_)           // 6912
#define NTHREADS 256
#define SPLIT 3
#define PIX_PER (HW_ / SPLIT)   // 2304 = 9 * 256
#define PW (W_ + 3)             // 75: col 0 zero, cols 1..72 data, 73,74 zero
#define PH (H_ + 3)             // 99: row 0 zero, rows 1..96 data, 97,98 zero

// Branchless bilinear gather from zero-padded smem plane.
// Clamping py to [-1, H] / px to [-1, W] is exact: at/beyond the clamp every
// real texel's interpolation weight is 0 and the padding reads 0.
__device__ __forceinline__ float bilerp(const float* __restrict__ sx,
                                        float py, float px)
{
    py = fminf(fmaxf(py, -1.0f), (float)H_);
    px = fminf(fmaxf(px, -1.0f), (float)W_);
    const float y0f = floorf(py);
    const float x0f = floorf(px);
    const float wy = py - y0f;
    const float wx = px - x0f;
    const int idx = ((int)y0f + 1) * PW + ((int)x0f + 1);
    const float s00 = sx[idx];
    const float s01 = sx[idx + 1];
    const float s10 = sx[idx + PW];
    const float s11 = sx[idx + PW + 1];
    const float vt = fmaf(wx, s01 - s00, s00);
    const float vb = fmaf(wx, s11 - s10, s10);
    return fmaf(wy, vb - vt, vt);
}

__global__ __launch_bounds__(NTHREADS, 7)
void dcn_kernel(const float* __restrict__ x,
                const float* __restrict__ off,
                const float* __restrict__ mask,
                const float* __restrict__ weight,
                const float* __restrict__ bias,
                float* __restrict__ out)
{
    __shared__ float sx[PH * PW];       // 29,700 B zero-padded (b,c) plane

    const int s  = blockIdx.x;          // plane split index 0..SPLIT-1
    const int bc = blockIdx.y;          // b * C_ + c
    const int c  = bc % C_;
    const int b  = bc / C_;
    const int tid = threadIdx.x;

    // Zero ONLY the padding (513 words): pad rows 0,97,98 and pad cols
    // 0,73,74 of rows 1..96. Interior is covered by the fill below; the
    // regions are disjoint, so one __syncthreads() after both suffices.
    if (tid < 75)                  sx[tid] = 0.0f;                    // row 0
    else if (tid < 225)            sx[97 * PW + (tid - 75)] = 0.0f;   // rows 97,98
    for (int i = tid; i < 3 * H_; i += NTHREADS) {                    // side cols
        const int r  = i / 3 + 1;
        const int c3 = i - (r - 1) * 3;
        sx[r * PW + ((c3 == 0) ? 0 : (W_ + c3))] = 0.0f;
    }

    float wk[KK_];
    #pragma unroll
    for (int k = 0; k < KK_; ++k)
        wk[k] = weight[c * KK_ + k];
    const float bv = bias[c];

    // Fill interior. Sibling CTAs (same bc, different s) are adjacent in the
    // grid -> the x plane hits L2 after the first CTA reads it.
    const float* __restrict__ xp = x + (size_t)bc * HW_;
    #pragma unroll
    for (int i = tid; i < HW_; i += NTHREADS) {
        const int r = i / W_;
        const int cc = i - r * W_;
        sx[(r + 1) * PW + (cc + 1)] = xp[i];
    }
    __syncthreads();

    const float* __restrict__ offb = off  + (size_t)b * (2 * C_ * KK_ * HW_)
                                          + (size_t)(c * KK_) * 2 * HW_;
    const float* __restrict__ mb   = mask + (size_t)b * (C_ * KK_ * HW_)
                                          + (size_t)(c * KK_) * HW_;
    float* __restrict__ op = out + (size_t)bc * HW_;

    // Scalar pixels: p = p0 + 256*i -> gather base addresses unit-stride
    // across the warp. 9 pixels per thread.
    const int p0   = s * PIX_PER + tid;
    const int pend = (s + 1) * PIX_PER;

    int h = p0 / W_;
    int w = p0 - h * W_;
    // stride 256 = 3*W_ + 40
    for (int p = p0; p < pend; p += NTHREADS) {
        // Front-batched loads (fully unrolled, no branches -> high MLP).
        float dy[KK_], dx[KK_], m[KK_];
        #pragma unroll
        for (int k = 0; k < KK_; ++k) {
            dy[k] = __ldcs(offb + (size_t)(2 * k    ) * HW_ + p);
            dx[k] = __ldcs(offb + (size_t)(2 * k + 1) * HW_ + p);
            m[k]  = __ldcs(mb   + (size_t)k           * HW_ + p);
        }

        const float hy  = (float)(h - 1);
        const float wxx = (float)(w - 1);

        float acc = 0.0f;
        #pragma unroll
        for (int k = 0; k < KK_; ++k) {
            const int ky = k / 3;
            const int kx = k - ky * 3;
            const float v = bilerp(sx, hy + (float)ky + dy[k],
                                       wxx + (float)kx + dx[k]);
            acc = fmaf(m[k] * v, wk[k], acc);
        }

        __stcs(op + p, acc + bv);

        // advance (h, w) by 256 pixels: 256 = 3*W_ + 40
        h += 3; w += 40;
        if (w >= W_) { w -= W_; ++h; }
    }
}

extern "C" void kernel_launch(void* const* d_in, const int* in_sizes, int n_in,
                              void* d_out, int out_size)
{
    const float* x      = (const float*)d_in[0];
    const float* off    = (const float*)d_in[1];
    const float* mask   = (const float*)d_in[2];
    const float* weight = (const float*)d_in[3];
    const float* bias   = (const float*)d_in[4];
    float* out          = (float*)d_out;

    dim3 grid(SPLIT, B_ * C_);
    dcn_kernel<<<grid, NTHREADS>>>(x, off, mask, weight, bias, out);
}

// round 15
// speedup vs baseline: 1.3403x; 1.3403x over previous
#include <cuda_runtime.h>

// DeformableCONV: modulated deformable conv v2, depthwise (groups = C).
// x:       (B, C, H, W)           f32
// offsets: (B, 2*C*KK, H, W)      f32   layout (B, C, KK, 2{dy,dx}, H, W)
// mask:    (B, C*KK, H, W)        f32   layout (B, C, KK, H, W)
// weight:  (C, 1, K, K)           f32
// bias:    (C,)                   f32
// out:     (B, C, H, W)           f32

#define B_ 32
#define C_ 17
#define H_ 96
#define W_ 72
#define KK_ 9
#define HW_ (H_ * W_)           // 6912
#define NTHREADS 256
#define SPLIT 3
#define PIX_PER (HW_ / SPLIT)   // 2304 = 9 * 256
#define PW (W_ + 3)             // 75: col 0 zero, cols 1..72 data, 73,74 zero
#define PH (H_ + 3)             // 99: row 0 zero, rows 1..96 data, 97,98 zero

// Branchless bilinear gather from zero-padded smem plane.
// Clamping py to [-1, H] / px to [-1, W] is exact: at/beyond the clamp every
// real texel's interpolation weight is 0 and the padding reads 0.
__device__ __forceinline__ float bilerp(const float* __restrict__ sx,
                                        float py, float px)
{
    py = fminf(fmaxf(py, -1.0f), (float)H_);
    px = fminf(fmaxf(px, -1.0f), (float)W_);
    const float y0f = floorf(py);
    const float x0f = floorf(px);
    const float wy = py - y0f;
    const float wx = px - x0f;
    const int idx = ((int)y0f + 1) * PW + ((int)x0f + 1);
    const float s00 = sx[idx];
    const float s01 = sx[idx + 1];
    const float s10 = sx[idx + PW];
    const float s11 = sx[idx + PW + 1];
    const float vt = fmaf(wx, s01 - s00, s00);
    const float vb = fmaf(wx, s11 - s10, s10);
    return fmaf(wy, vb - vt, vt);
}

__global__ __launch_bounds__(NTHREADS, 6)
void dcn_kernel(const float* __restrict__ x,
                const float* __restrict__ off,
                const float* __restrict__ mask,
                const float* __restrict__ weight,
                const float* __restrict__ bias,
                float* __restrict__ out)
{
    __shared__ float sx[PH * PW];       // 29,700 B zero-padded (b,c) plane

    const int s  = blockIdx.x;          // plane split index 0..SPLIT-1
    const int bc = blockIdx.y;          // b * C_ + c
    const int c  = bc % C_;
    const int b  = bc / C_;
    const int tid = threadIdx.x;

    // Zero ONLY the padding (513 words): pad rows 0,97,98 and pad cols
    // 0,73,74 of rows 1..96. Interior is covered by the fill below; the
    // regions are disjoint, so one __syncthreads() after both suffices.
    if (tid < 75)                  sx[tid] = 0.0f;                    // row 0
    else if (tid < 225)            sx[97 * PW + (tid - 75)] = 0.0f;   // rows 97,98
    for (int i = tid; i < 3 * H_; i += NTHREADS) {                    // side cols
        const int r  = i / 3 + 1;
        const int c3 = i - (r - 1) * 3;
        sx[r * PW + ((c3 == 0) ? 0 : (W_ + c3))] = 0.0f;
    }

    float wk[KK_];
    #pragma unroll
    for (int k = 0; k < KK_; ++k)
        wk[k] = weight[c * KK_ + k];
    const float bv = bias[c];

    // Fill interior. Sibling CTAs (same bc, different s) are adjacent in the
    // grid -> the x plane hits L2 after the first CTA reads it.
    const float* __restrict__ xp = x + (size_t)bc * HW_;
    #pragma unroll
    for (int i = tid; i < HW_; i += NTHREADS) {
        const int r = i / W_;
        const int cc = i - r * W_;
        sx[(r + 1) * PW + (cc + 1)] = xp[i];
    }
    __syncthreads();

    const float* __restrict__ offb = off  + (size_t)b * (2 * C_ * KK_ * HW_)
                                          + (size_t)(c * KK_) * 2 * HW_;
    const float* __restrict__ mb   = mask + (size_t)b * (C_ * KK_ * HW_)
                                          + (size_t)(c * KK_) * HW_;
    float* __restrict__ op = out + (size_t)bc * HW_;

    // Scalar pixels: p = p0 + 256*i -> gather base addresses unit-stride
    // across the warp. 9 pixels per thread.
    const int p0   = s * PIX_PER + tid;
    const int pend = (s + 1) * PIX_PER;

    int h = p0 / W_;
    int w = p0 - h * W_;
    // stride 256 = 3*W_ + 40
    for (int p = p0; p < pend; p += NTHREADS) {
        // Front-batched loads (fully unrolled, no branches -> MLP ~27).
        float dy[KK_], dx[KK_], m[KK_];
        #pragma unroll
        for (int k = 0; k < KK_; ++k) {
            dy[k] = __ldcs(offb + (size_t)(2 * k    ) * HW_ + p);
            dx[k] = __ldcs(offb + (size_t)(2 * k + 1) * HW_ + p);
            m[k]  = __ldcs(mb   + (size_t)k           * HW_ + p);
        }

        const float hy  = (float)(h - 1);
        const float wxx = (float)(w - 1);

        float acc = 0.0f;
        #pragma unroll
        for (int k = 0; k < KK_; ++k) {
            const int ky = k / 3;
            const int kx = k - ky * 3;
            const float v = bilerp(sx, hy + (float)ky + dy[k],
                                       wxx + (float)kx + dx[k]);
            acc = fmaf(m[k] * v, wk[k], acc);
        }

        __stcs(op + p, acc + bv);

        // advance (h, w) by 256 pixels: 256 = 3*W_ + 40
        h += 3; w += 40;
        if (w >= W_) { w -= W_; ++h; }
    }
}

extern "C" void kernel_launch(void* const* d_in, const int* in_sizes, int n_in,
                              void* d_out, int out_size)
{
    const float* x      = (const float*)d_in[0];
    const float* off    = (const float*)d_in[1];
    const float* mask   = (const float*)d_in[2];
    const float* weight = (const float*)d_in[3];
    const float* bias   = (const float*)d_in[4];
    float* out          = (float*)d_out;

    dim3 grid(SPLIT, B_ * C_);
    dcn_kernel<<<grid, NTHREADS>>>(x, off, mask, weight, bias, out);
}

// round 16
// speedup vs baseline: 1.3796x; 1.0294x over previous
#include <cuda_runtime.h>
#include <cuda_fp16.h>

// DeformableCONV: modulated deformable conv v2, depthwise (groups = C).
// x:       (B, C, H, W)           f32
// offsets: (B, 2*C*KK, H, W)      f32   layout (B, C, KK, 2{dy,dx}, H, W)
// mask:    (B, C*KK, H, W)        f32   layout (B, C, KK, H, W)
// weight:  (C, 1, K, K)           f32
// bias:    (C,)                   f32
// out:     (B, C, H, W)           f32
//
// Plane is stored in smem as PAIRED fp16: word i of padded row r holds
// (texel_i, texel_{i+1}) as __half2. One LDS.32 fetches both row-neighbors
// of a bilinear corner pair -> 18 LDS/pixel instead of 36, halving smem
// crossbar bytes + conflict exposure. Texels fp16, all weights/lerp fp32.

#define B_ 32
#define C_ 17
#define H_ 96
#define W_ 72
#define KK_ 9
#define HW_ (H_ * W_)           // 6912
#define NTHREADS 256
#define SPLIT 3
#define PIX_PER (HW_ / SPLIT)   // 2304 = 9 * 256
#define PW 75                   // padded cols: v0=0, v1..72=data, v73,v74=0
#define PH 99                   // padded rows: 0 zero, 1..96 data, 97,98 zero

// Branchless bilinear gather from zero-padded paired-fp16 smem plane.
// Clamping py to [-1, H] / px to [-1, W] is exact: at/beyond the clamp every
// real texel's interpolation weight is 0 and the padding reads 0.
__device__ __forceinline__ float bilerp(const __half2* __restrict__ sx,
                                        float py, float px)
{
    py = fminf(fmaxf(py, -1.0f), (float)H_);
    px = fminf(fmaxf(px, -1.0f), (float)W_);
    const float y0f = floorf(py);
    const float x0f = floorf(px);
    const float wy = py - y0f;
    const float wx = px - x0f;
    const int idx = ((int)y0f + 1) * PW + ((int)x0f + 1);
    const float2 t = __half22float2(sx[idx]);        // (s00, s01)
    const float2 b = __half22float2(sx[idx + PW]);   // (s10, s11)
    const float vt = fmaf(wx, t.y - t.x, t.x);
    const float vb = fmaf(wx, b.y - b.x, b.x);
    return fmaf(wy, vb - vt, vt);
}

__global__ __launch_bounds__(NTHREADS, 6)
void dcn_kernel(const float* __restrict__ x,
                const float* __restrict__ off,
                const float* __restrict__ mask,
                const float* __restrict__ weight,
                const float* __restrict__ bias,
                float* __restrict__ out)
{
    __shared__ __half2 sx[PH * PW];     // 29,700 B paired-fp16 padded plane

    const int s  = blockIdx.x;          // plane split index 0..SPLIT-1
    const int bc = blockIdx.y;          // b * C_ + c
    const int c  = bc % C_;
    const int b  = bc / C_;
    const int tid = threadIdx.x;

    // Zero pad rows 0, 97, 98 (225 words). Column padding is produced by the
    // predicated fill below; regions disjoint -> one __syncthreads().
    if (tid < 75)       sx[tid]                 = __float2half2_rn(0.0f);
    else if (tid < 225) sx[97 * PW + (tid - 75)] = __float2half2_rn(0.0f);

    float wk[KK_];
    #pragma unroll
    for (int k = 0; k < KK_; ++k)
        wk[k] = weight[c * KK_ + k];
    const float bv = bias[c];

    // Fill rows 1..96: word i = (v_i, v_{i+1}), v_j = data for j in [1,72],
    // else 0. Two overlapping coalesced LDG streams (L1-served).
    const float* __restrict__ xp = x + (size_t)bc * HW_;
    for (int e = tid; e < H_ * PW; e += NTHREADS) {
        const int r = e / PW;           // data row 0..95
        const int i = e - r * PW;       // word col 0..74
        const float a  = (i >= 1 && i <= 72) ? xp[r * W_ + (i - 1)] : 0.0f;
        const float bb = (i <= 71)           ? xp[r * W_ + i]       : 0.0f;
        sx[(r + 1) * PW + i] = __floats2half2_rn(a, bb);
    }
    __syncthreads();

    const float* __restrict__ offb = off  + (size_t)b * (2 * C_ * KK_ * HW_)
                                          + (size_t)(c * KK_) * 2 * HW_;
    const float* __restrict__ mb   = mask + (size_t)b * (C_ * KK_ * HW_)
                                          + (size_t)(c * KK_) * HW_;
    float* __restrict__ op = out + (size_t)bc * HW_;

    // Scalar pixels: p = p0 + 256*i -> gather base addresses unit-stride
    // across the warp. 9 pixels per thread.
    const int p0   = s * PIX_PER + tid;
    const int pend = (s + 1) * PIX_PER;

    int h = p0 / W_;
    int w = p0 - h * W_;
    // stride 256 = 3*W_ + 40
    for (int p = p0; p < pend; p += NTHREADS) {
        // Front-batched loads (fully unrolled, no branches -> MLP ~27).
        float dy[KK_], dx[KK_], m[KK_];
        #pragma unroll
        for (int k = 0; k < KK_; ++k) {
            dy[k] = __ldcs(offb + (size_t)(2 * k    ) * HW_ + p);
            dx[k] = __ldcs(offb + (size_t)(2 * k + 1) * HW_ + p);
            m[k]  = __ldcs(mb   + (size_t)k           * HW_ + p);
        }

        const float hy  = (float)(h - 1);
        const float wxx = (float)(w - 1);

        float acc = 0.0f;
        #pragma unroll
        for (int k = 0; k < KK_; ++k) {
            const int ky = k / 3;
            const int kx = k - ky * 3;
            const float v = bilerp(sx, hy + (float)ky + dy[k],
                                       wxx + (float)kx + dx[k]);
            acc = fmaf(m[k] * v, wk[k], acc);
        }

        __stcs(op + p, acc + bv);

        // advance (h, w) by 256 pixels: 256 = 3*W_ + 40
        h += 3; w += 40;
        if (w >= W_) { w -= W_; ++h; }
    }
}

extern "C" void kernel_launch(void* const* d_in, const int* in_sizes, int n_in,
                              void* d_out, int out_size)
{
    const float* x      = (const float*)d_in[0];
    const float* off    = (const float*)d_in[1];
    const float* mask   = (const float*)d_in[2];
    const float* weight = (const float*)d_in[3];
    const float* bias   = (const float*)d_in[4];
    float* out          = (float*)d_out;

    dim3 grid(SPLIT, B_ * C_);
    dcn_kernel<<<grid, NTHREADS>>>(x, off, mask, weight, bias, out);
}